// round 2
// baseline (speedup 1.0000x reference)
#include <cuda_runtime.h>
#include <math.h>

// ---------------------------------------------------------------------------
// Problem constants
// ---------------------------------------------------------------------------
namespace {
constexpr int B_  = 16;
constexpr int TT_ = 128;
constexpr int TS_ = 512;
constexpr int L_  = TT_ + TS_ + 2;   // 642
constexpr int D_  = 1024;
constexpr int H_  = 16;
constexpr int HD_ = 64;
constexpr int F_  = 4096;
constexpr int NL_ = 4;
constexpr int M_  = B_ * L_;         // 10272
constexpr int SMEM_ATT = (4096 * 3 + 64 * 68 + 64) * 4;  // 66816 bytes
}

// ---------------------------------------------------------------------------
// Scratch (allocation-free: __device__ globals)
// ---------------------------------------------------------------------------
__device__ float g_x  [(size_t)M_ * D_];
__device__ float g_q  [(size_t)M_ * D_];
__device__ float g_k  [(size_t)M_ * D_];
__device__ float g_v  [(size_t)M_ * D_];
__device__ float g_att[(size_t)M_ * D_];
__device__ float g_y  [(size_t)M_ * D_];
__device__ float g_h  [(size_t)M_ * F_];
__device__ int   g_tlen[B_];
__device__ int   g_slen[B_];
__device__ int   g_pad[M_];

// ---------------------------------------------------------------------------
// Mask length computation with on-device dtype detection.
// bool masks may arrive as uint8, int32, or float32; detect from byte pattern:
//   any byte == 0x3F            -> float32 (1.0f = 00 00 80 3F)
//   any byte == 1 at i%4 != 0   -> uint8   (int32 1 only has byte at i%4==0)
//   else                        -> int32 (word path; also fine for float32)
// ---------------------------------------------------------------------------
__global__ void lengths_kernel(const void* tmask, const void* smask) {
    int which = blockIdx.x;                 // 0 = text, 1 = speech
    const void* mask = which ? smask : tmask;
    int T = which ? TS_ : TT_;
    int* lens = which ? g_slen : g_tlen;
    int N = B_ * T;

    __shared__ int f3F, fMis;
    __shared__ int cnt[B_];
    int tid = threadIdx.x;
    if (tid == 0) { f3F = 0; fMis = 0; }
    if (tid < B_) cnt[tid] = 0;
    __syncthreads();

    const unsigned char* bytes = (const unsigned char*)mask;
    int l3 = 0, lm = 0;
    for (int i = tid; i < N; i += blockDim.x) {
        unsigned char c = bytes[i];
        if (c == 0x3F) l3 = 1;
        if (c == 1 && (i & 3)) lm = 1;
    }
    if (l3) atomicOr(&f3F, 1);
    if (lm) atomicOr(&fMis, 1);
    __syncthreads();

    if (fMis && !f3F) {
        // uint8 storage
        for (int i = tid; i < N; i += blockDim.x)
            if (bytes[i] == 0) atomicAdd(&cnt[i / T], 1);
    } else {
        // 32-bit storage (int32 or float32): zero iff word == 0
        const unsigned int* w = (const unsigned int*)mask;
        for (int i = tid; i < N; i += blockDim.x)
            if (w[i] == 0u) atomicAdd(&cnt[i / T], 1);
    }
    __syncthreads();
    if (tid < B_) lens[tid] = cnt[tid];
}

// ---------------------------------------------------------------------------
// Build concatenated sequence x[b, pos, :] and key-padding mask
// ---------------------------------------------------------------------------
__global__ void build_x_kernel(const float* __restrict__ text,
                               const float* __restrict__ speech,
                               const float* __restrict__ cls,
                               const float* __restrict__ sep) {
    int pos = blockIdx.x, b = blockIdx.y;
    int tl = g_tlen[b], sl = g_slen[b];
    float* xr = &g_x[((size_t)(b * L_) + pos) * D_];
    if (threadIdx.x == 0)
        g_pad[b * L_ + pos] = (pos >= 2 + tl + sl) ? 1 : 0;

    const float* s;
    if (pos == 0)                 s = cls;
    else if (pos < 1 + tl)        s = &text  [((size_t)(pos - 1) * B_ + b) * D_];
    else if (pos == 1 + tl)       s = sep;
    else if (pos < 2 + tl + sl)   s = &speech[((size_t)(pos - 2 - tl) * B_ + b) * D_];
    else                          s = nullptr;

    for (int d = threadIdx.x; d < D_; d += blockDim.x)
        xr[d] = s ? s[d] : 0.f;
}

// ---------------------------------------------------------------------------
// SGEMM: C[M,N] = A[M,K] @ W[K,N] + bias[N], optional ReLU.
// 64x64 blocktile, BK=16, 256 threads, 4x4 register fragments.
// ---------------------------------------------------------------------------
template <int RELU>
__global__ __launch_bounds__(256) void gemm_kernel(
    const float* __restrict__ A, const float* __restrict__ W,
    const float* __restrict__ bias, float* __restrict__ C,
    int Mn, int Nn, int Kn) {
    __shared__ float As[16][64];   // As[k][m]
    __shared__ float Bs[16][64];   // Bs[k][n]

    int tid = threadIdx.x;
    int tx = tid & 15, ty = tid >> 4;
    int m0 = blockIdx.y * 64, n0 = blockIdx.x * 64;

    float acc[4][4] = {};
    int arow = tid >> 2, acol = (tid & 3) * 4;
    int brow = tid >> 4, bcol = (tid & 15) * 4;

    for (int k0 = 0; k0 < Kn; k0 += 16) {
        float4 av = make_float4(0.f, 0.f, 0.f, 0.f);
        if (m0 + arow < Mn)
            av = *(const float4*)&A[(size_t)(m0 + arow) * Kn + k0 + acol];
        As[acol + 0][arow] = av.x;
        As[acol + 1][arow] = av.y;
        As[acol + 2][arow] = av.z;
        As[acol + 3][arow] = av.w;
        *(float4*)&Bs[brow][bcol] =
            *(const float4*)&W[(size_t)(k0 + brow) * Nn + n0 + bcol];
        __syncthreads();

        #pragma unroll
        for (int kk = 0; kk < 16; kk++) {
            float4 a = *(float4*)&As[kk][ty * 4];
            float4 b = *(float4*)&Bs[kk][tx * 4];
            float ar[4] = {a.x, a.y, a.z, a.w};
            float br[4] = {b.x, b.y, b.z, b.w};
            #pragma unroll
            for (int i = 0; i < 4; i++)
                #pragma unroll
                for (int j = 0; j < 4; j++)
                    acc[i][j] += ar[i] * br[j];
        }
        __syncthreads();
    }

    #pragma unroll
    for (int i = 0; i < 4; i++) {
        int m = m0 + ty * 4 + i;
        if (m < Mn) {
            float4 vv;
            float* pv = (float*)&vv;
            #pragma unroll
            for (int j = 0; j < 4; j++) {
                float t = acc[i][j] + bias[n0 + tx * 4 + j];
                if (RELU) t = fmaxf(t, 0.f);
                pv[j] = t;
            }
            *(float4*)&C[(size_t)m * Nn + n0 + tx * 4] = vv;
        }
    }
}

// ---------------------------------------------------------------------------
// Fused flash attention. One block per (q-tile 64, head, batch).
// Q scaled by HD^-0.5 at load. Keys masked by pad mask / length.
// ---------------------------------------------------------------------------
__global__ __launch_bounds__(256) void attn_kernel() {
    extern __shared__ float sm[];
    float* Qs = sm;                    // [64][64] Qs[d*64+q]  (transposed)
    float* Ks = sm + 4096;             // [64][64] Ks[d*64+k]  (transposed)
    float* Vs = sm + 8192;             // [64][64] Vs[k*64+d]
    float* Pt = sm + 12288;            // [64][68] Pt[k*68+q]  (padded stride)
    float* km = sm + 12288 + 64 * 68;  // [64] key mask (1 = masked)

    int tid = threadIdx.x;
    int tx = tid & 15, ty = tid >> 4;
    int qt = blockIdx.x, h = blockIdx.y, b = blockIdx.z;
    int q0 = qt * 64;
    int ldr = tid >> 2;            // 0..63 (row loaded by this thread)
    int cb  = (tid & 3) * 16;      // column base (16 floats per thread)

    // Load Q tile transposed, pre-scaled
    {
        int qrow = q0 + ldr;
        bool valid = qrow < L_;
        const float* src = &g_q[((size_t)(b * L_) + (valid ? qrow : 0)) * D_ + h * HD_];
        #pragma unroll
        for (int u = 0; u < 16; u += 4) {
            float4 vv = valid ? *(const float4*)&src[cb + u]
                              : make_float4(0.f, 0.f, 0.f, 0.f);
            Qs[(cb + u + 0) * 64 + ldr] = vv.x * 0.125f;
            Qs[(cb + u + 1) * 64 + ldr] = vv.y * 0.125f;
            Qs[(cb + u + 2) * 64 + ldr] = vv.z * 0.125f;
            Qs[(cb + u + 3) * 64 + ldr] = vv.w * 0.125f;
        }
    }

    float o[4][4] = {};
    float mr[4]   = {-1e30f, -1e30f, -1e30f, -1e30f};
    float lsum[4] = {0.f, 0.f, 0.f, 0.f};

    const int NKT = (L_ + 63) / 64;  // 11
    for (int kt = 0; kt < NKT; kt++) {
        int k0 = kt * 64;
        __syncthreads();  // protect Vs/Pt/Qs from previous iter before overwrite

        {
            int krow = k0 + ldr;
            bool valid = krow < L_;
            const float* ksrc = &g_k[((size_t)(b * L_) + (valid ? krow : 0)) * D_ + h * HD_];
            const float* vsrc = &g_v[((size_t)(b * L_) + (valid ? krow : 0)) * D_ + h * HD_];
            #pragma unroll
            for (int u = 0; u < 16; u += 4) {
                float4 vv = valid ? *(const float4*)&ksrc[cb + u]
                                  : make_float4(0.f, 0.f, 0.f, 0.f);
                Ks[(cb + u + 0) * 64 + ldr] = vv.x;
                Ks[(cb + u + 1) * 64 + ldr] = vv.y;
                Ks[(cb + u + 2) * 64 + ldr] = vv.z;
                Ks[(cb + u + 3) * 64 + ldr] = vv.w;
            }
            #pragma unroll
            for (int u = 0; u < 16; u += 4) {
                float4 vv = valid ? *(const float4*)&vsrc[cb + u]
                                  : make_float4(0.f, 0.f, 0.f, 0.f);
                *(float4*)&Vs[ldr * 64 + cb + u] = vv;
            }
        }
        if (tid < 64) {
            int kp = k0 + tid;
            km[tid] = (kp < L_ && g_pad[b * L_ + kp] == 0) ? 0.f : 1.f;
        }
        __syncthreads();

        // S = Q^T K  (64x64, each thread 4x4)
        float s[4][4] = {};
        #pragma unroll 8
        for (int d = 0; d < 64; d++) {
            float4 a  = *(float4*)&Qs[d * 64 + ty * 4];
            float4 bb = *(float4*)&Ks[d * 64 + tx * 4];
            float ar[4] = {a.x, a.y, a.z, a.w};
            float br[4] = {bb.x, bb.y, bb.z, bb.w};
            #pragma unroll
            for (int i = 0; i < 4; i++)
                #pragma unroll
                for (int j = 0; j < 4; j++)
                    s[i][j] += ar[i] * br[j];
        }

        float kmr[4];
        #pragma unroll
        for (int j = 0; j < 4; j++) kmr[j] = km[tx * 4 + j];
        #pragma unroll
        for (int i = 0; i < 4; i++)
            #pragma unroll
            for (int j = 0; j < 4; j++)
                if (kmr[j] != 0.f) s[i][j] = -1e9f;

        // Online softmax (row stats shared across the 16 tx lanes)
        #pragma unroll
        for (int i = 0; i < 4; i++) {
            float tmax = fmaxf(fmaxf(s[i][0], s[i][1]), fmaxf(s[i][2], s[i][3]));
            #pragma unroll
            for (int off = 8; off >= 1; off >>= 1)
                tmax = fmaxf(tmax, __shfl_xor_sync(0xffffffffu, tmax, off));
            float mnew  = fmaxf(mr[i], tmax);
            float alpha = expf(mr[i] - mnew);
            float rsum = 0.f;
            #pragma unroll
            for (int j = 0; j < 4; j++) {
                float p = expf(s[i][j] - mnew);
                s[i][j] = p;
                rsum += p;
            }
            #pragma unroll
            for (int off = 8; off >= 1; off >>= 1)
                rsum += __shfl_xor_sync(0xffffffffu, rsum, off);
            lsum[i] = lsum[i] * alpha + rsum;
            mr[i] = mnew;
            #pragma unroll
            for (int j = 0; j < 4; j++) o[i][j] *= alpha;
        }

        // Write P transposed for the PV GEMM
        #pragma unroll
        for (int j = 0; j < 4; j++)
            #pragma unroll
            for (int i = 0; i < 4; i++)
                Pt[(tx * 4 + j) * 68 + ty * 4 + i] = s[i][j];
        __syncthreads();

        // O += P V
        #pragma unroll 8
        for (int kk = 0; kk < 64; kk++) {
            float4 a  = *(float4*)&Pt[kk * 68 + ty * 4];
            float4 bb = *(float4*)&Vs[kk * 64 + tx * 4];
            float ar[4] = {a.x, a.y, a.z, a.w};
            float br[4] = {bb.x, bb.y, bb.z, bb.w};
            #pragma unroll
            for (int i = 0; i < 4; i++)
                #pragma unroll
                for (int j = 0; j < 4; j++)
                    o[i][j] += ar[i] * br[j];
        }
    }

    #pragma unroll
    for (int i = 0; i < 4; i++) {
        int qrow = q0 + ty * 4 + i;
        if (qrow < L_) {
            float inv = 1.f / lsum[i];
            float4 vv = make_float4(o[i][0] * inv, o[i][1] * inv,
                                    o[i][2] * inv, o[i][3] * inv);
            *(float4*)&g_att[((size_t)(b * L_) + qrow) * D_ + h * HD_ + tx * 4] = vv;
        }
    }
}

// ---------------------------------------------------------------------------
// x = LayerNorm(x + y) * s + b  (in place on g_x; y = g_y)
// ---------------------------------------------------------------------------
__global__ __launch_bounds__(256) void add_ln_kernel(const float* __restrict__ sc,
                                                     const float* __restrict__ bi) {
    int row = blockIdx.x;
    float* xr = &g_x[(size_t)row * D_];
    const float* yr = &g_y[(size_t)row * D_];
    __shared__ float red[256];
    int tid = threadIdx.x;

    float v[4];
    float s = 0.f;
    #pragma unroll
    for (int u = 0; u < 4; u++) {
        int d = tid + u * 256;
        v[u] = xr[d] + yr[d];
        s += v[u];
    }
    red[tid] = s;
    __syncthreads();
    for (int off = 128; off > 0; off >>= 1) {
        if (tid < off) red[tid] += red[tid + off];
        __syncthreads();
    }
    float mean = red[0] * (1.f / D_);
    __syncthreads();

    float s2 = 0.f;
    #pragma unroll
    for (int u = 0; u < 4; u++) { float dd = v[u] - mean; s2 += dd * dd; }
    red[tid] = s2;
    __syncthreads();
    for (int off = 128; off > 0; off >>= 1) {
        if (tid < off) red[tid] += red[tid + off];
        __syncthreads();
    }
    float var = red[0] * (1.f / D_);
    float inv = rsqrtf(var + 1e-5f);

    #pragma unroll
    for (int u = 0; u < 4; u++) {
        int d = tid + u * 256;
        xr[d] = (v[u] - mean) * inv * sc[d] + bi[d];
    }
}

// ---------------------------------------------------------------------------
// out[b] = dot(x[b, 0, :], out_w)
// ---------------------------------------------------------------------------
__global__ __launch_bounds__(256) void final_kernel(const float* __restrict__ ow,
                                                    float* __restrict__ out) {
    int b = blockIdx.x;
    __shared__ float red[256];
    const float* xr = &g_x[(size_t)(b * L_) * D_];
    int tid = threadIdx.x;
    float s = 0.f;
    for (int d = tid; d < D_; d += 256) s += xr[d] * ow[d];
    red[tid] = s;
    __syncthreads();
    for (int off = 128; off > 0; off >>= 1) {
        if (tid < off) red[tid] += red[tid + off];
        __syncthreads();
    }
    if (tid == 0) out[b] = red[0];
}

// ---------------------------------------------------------------------------
// Launch
// ---------------------------------------------------------------------------
extern "C" void kernel_launch(void* const* d_in, const int* in_sizes, int n_in,
                              void* d_out, int out_size) {
    const float* text   = (const float*)d_in[0];
    const float* speech = (const float*)d_in[1];
    const void*  tmask  = d_in[2];
    const void*  smask  = d_in[3];
    const float* cls    = (const float*)d_in[4];
    const float* sep    = (const float*)d_in[5];
    const float* Wq     = (const float*)d_in[6];
    const float* bq     = (const float*)d_in[7];
    const float* Wk     = (const float*)d_in[8];
    const float* bk     = (const float*)d_in[9];
    const float* Wv     = (const float*)d_in[10];
    const float* bv     = (const float*)d_in[11];
    const float* Wo     = (const float*)d_in[12];
    const float* bo     = (const float*)d_in[13];
    const float* ln1s   = (const float*)d_in[14];
    const float* ln1b   = (const float*)d_in[15];
    const float* f1w    = (const float*)d_in[16];
    const float* f1b    = (const float*)d_in[17];
    const float* f2w    = (const float*)d_in[18];
    const float* f2b    = (const float*)d_in[19];
    const float* ln2s   = (const float*)d_in[20];
    const float* ln2b   = (const float*)d_in[21];
    const float* outw   = (const float*)d_in[22];
    float* out = (float*)d_out;

    float *x, *q, *k, *v, *att, *y, *hbuf;
    cudaGetSymbolAddress((void**)&x,    g_x);
    cudaGetSymbolAddress((void**)&q,    g_q);
    cudaGetSymbolAddress((void**)&k,    g_k);
    cudaGetSymbolAddress((void**)&v,    g_v);
    cudaGetSymbolAddress((void**)&att,  g_att);
    cudaGetSymbolAddress((void**)&y,    g_y);
    cudaGetSymbolAddress((void**)&hbuf, g_h);

    cudaFuncSetAttribute(attn_kernel,
                         cudaFuncAttributeMaxDynamicSharedMemorySize, SMEM_ATT);

    lengths_kernel<<<2, 256>>>(tmask, smask);
    build_x_kernel<<<dim3(L_, B_), 256>>>(text, speech, cls, sep);

    dim3 gD(D_ / 64, (M_ + 63) / 64);
    dim3 gF(F_ / 64, (M_ + 63) / 64);
    dim3 gAtt((L_ + 63) / 64, H_, B_);

    for (int l = 0; l < NL_; l++) {
        gemm_kernel<0><<<gD, 256>>>(x, Wq + (size_t)l * D_ * D_, bq + l * D_, q, M_, D_, D_);
        gemm_kernel<0><<<gD, 256>>>(x, Wk + (size_t)l * D_ * D_, bk + l * D_, k, M_, D_, D_);
        gemm_kernel<0><<<gD, 256>>>(x, Wv + (size_t)l * D_ * D_, bv + l * D_, v, M_, D_, D_);
        attn_kernel<<<gAtt, 256, SMEM_ATT>>>();
        gemm_kernel<0><<<gD, 256>>>(att, Wo + (size_t)l * D_ * D_, bo + l * D_, y, M_, D_, D_);
        add_ln_kernel<<<M_, 256>>>(ln1s + l * D_, ln1b + l * D_);
        gemm_kernel<1><<<gF, 256>>>(x, f1w + (size_t)l * D_ * F_, f1b + l * F_, hbuf, M_, F_, D_);
        gemm_kernel<0><<<gD, 256>>>(hbuf, f2w + (size_t)l * F_ * D_, f2b + l * D_, y, M_, D_, F_);
        add_ln_kernel<<<M_, 256>>>(ln2s + l * D_, ln2b + l * D_);
    }
    final_kernel<<<B_, 256>>>(outw, out);
}

// round 3
// speedup vs baseline: 1.0015x; 1.0015x over previous
#include <cuda_runtime.h>
#include <math.h>

// ---------------------------------------------------------------------------
// Problem constants
// ---------------------------------------------------------------------------
namespace {
constexpr int B_  = 16;
constexpr int TT_ = 128;
constexpr int TS_ = 512;
constexpr int L_  = TT_ + TS_ + 2;   // 642
constexpr int D_  = 1024;
constexpr int H_  = 16;
constexpr int HD_ = 64;
constexpr int F_  = 4096;
constexpr int NL_ = 4;
constexpr int M_  = B_ * L_;         // 10272
constexpr int SMEM_ATT = (4096 * 3 + 64 * 68 + 64) * 4;  // 66816 bytes
}

// ---------------------------------------------------------------------------
// Scratch (allocation-free: __device__ globals)
// ---------------------------------------------------------------------------
__device__ float g_x  [(size_t)M_ * D_];
__device__ float g_q  [(size_t)M_ * D_];
__device__ float g_k  [(size_t)M_ * D_];
__device__ float g_v  [(size_t)M_ * D_];
__device__ float g_att[(size_t)M_ * D_];
__device__ float g_y  [(size_t)M_ * D_];
__device__ float g_h  [(size_t)M_ * F_];
__device__ int   g_tlen[B_];
__device__ int   g_slen[B_];
__device__ int   g_pad[M_];

// ---------------------------------------------------------------------------
// Mask length computation with on-device dtype detection.
// bool masks may arrive as uint8, int32, or float32; detect from byte pattern:
//   any byte == 0x3F            -> float32 (1.0f = 00 00 80 3F)
//   any byte == 1 at i%4 != 0   -> uint8   (int32 1 only has byte at i%4==0)
//   else                        -> int32 (word path; also fine for float32)
// ---------------------------------------------------------------------------
__global__ void lengths_kernel(const void* tmask, const void* smask) {
    int which = blockIdx.x;                 // 0 = text, 1 = speech
    const void* mask = which ? smask : tmask;
    int T = which ? TS_ : TT_;
    int* lens = which ? g_slen : g_tlen;
    int N = B_ * T;

    __shared__ int f3F, fMis;
    __shared__ int cnt[B_];
    int tid = threadIdx.x;
    if (tid == 0) { f3F = 0; fMis = 0; }
    if (tid < B_) cnt[tid] = 0;
    __syncthreads();

    const unsigned char* bytes = (const unsigned char*)mask;
    int l3 = 0, lm = 0;
    for (int i = tid; i < N; i += blockDim.x) {
        unsigned char c = bytes[i];
        if (c == 0x3F) l3 = 1;
        if (c == 1 && (i & 3)) lm = 1;
    }
    if (l3) atomicOr(&f3F, 1);
    if (lm) atomicOr(&fMis, 1);
    __syncthreads();

    if (fMis && !f3F) {
        // uint8 storage
        for (int i = tid; i < N; i += blockDim.x)
            if (bytes[i] == 0) atomicAdd(&cnt[i / T], 1);
    } else {
        // 32-bit storage (int32 or float32): zero iff word == 0
        const unsigned int* w = (const unsigned int*)mask;
        for (int i = tid; i < N; i += blockDim.x)
            if (w[i] == 0u) atomicAdd(&cnt[i / T], 1);
    }
    __syncthreads();
    if (tid < B_) lens[tid] = cnt[tid];
}

// ---------------------------------------------------------------------------
// Build concatenated sequence x[b, pos, :] and key-padding mask
// ---------------------------------------------------------------------------
__global__ void build_x_kernel(const float* __restrict__ text,
                               const float* __restrict__ speech,
                               const float* __restrict__ cls,
                               const float* __restrict__ sep) {
    int pos = blockIdx.x, b = blockIdx.y;
    int tl = g_tlen[b], sl = g_slen[b];
    float* xr = &g_x[((size_t)(b * L_) + pos) * D_];
    if (threadIdx.x == 0)
        g_pad[b * L_ + pos] = (pos >= 2 + tl + sl) ? 1 : 0;

    const float* s;
    if (pos == 0)                 s = cls;
    else if (pos < 1 + tl)        s = &text  [((size_t)(pos - 1) * B_ + b) * D_];
    else if (pos == 1 + tl)       s = sep;
    else if (pos < 2 + tl + sl)   s = &speech[((size_t)(pos - 2 - tl) * B_ + b) * D_];
    else                          s = nullptr;

    for (int d = threadIdx.x; d < D_; d += blockDim.x)
        xr[d] = s ? s[d] : 0.f;
}

// ---------------------------------------------------------------------------
// SGEMM: C[M,N] = A[M,K] @ W[K,N] + bias[N], optional ReLU.
// 64x64 blocktile, BK=16, 256 threads, 4x4 register fragments.
// ---------------------------------------------------------------------------
template <int RELU>
__global__ __launch_bounds__(256) void gemm_kernel(
    const float* __restrict__ A, const float* __restrict__ W,
    const float* __restrict__ bias, float* __restrict__ C,
    int Mn, int Nn, int Kn) {
    __shared__ float As[16][64];   // As[k][m]
    __shared__ float Bs[16][64];   // Bs[k][n]

    int tid = threadIdx.x;
    int tx = tid & 15, ty = tid >> 4;
    int m0 = blockIdx.y * 64, n0 = blockIdx.x * 64;

    float acc[4][4] = {};
    int arow = tid >> 2, acol = (tid & 3) * 4;
    int brow = tid >> 4, bcol = (tid & 15) * 4;

    for (int k0 = 0; k0 < Kn; k0 += 16) {
        float4 av = make_float4(0.f, 0.f, 0.f, 0.f);
        if (m0 + arow < Mn)
            av = *(const float4*)&A[(size_t)(m0 + arow) * Kn + k0 + acol];
        As[acol + 0][arow] = av.x;
        As[acol + 1][arow] = av.y;
        As[acol + 2][arow] = av.z;
        As[acol + 3][arow] = av.w;
        *(float4*)&Bs[brow][bcol] =
            *(const float4*)&W[(size_t)(k0 + brow) * Nn + n0 + bcol];
        __syncthreads();

        #pragma unroll
        for (int kk = 0; kk < 16; kk++) {
            float4 a = *(float4*)&As[kk][ty * 4];
            float4 b = *(float4*)&Bs[kk][tx * 4];
            float ar[4] = {a.x, a.y, a.z, a.w};
            float br[4] = {b.x, b.y, b.z, b.w};
            #pragma unroll
            for (int i = 0; i < 4; i++)
                #pragma unroll
                for (int j = 0; j < 4; j++)
                    acc[i][j] += ar[i] * br[j];
        }
        __syncthreads();
    }

    #pragma unroll
    for (int i = 0; i < 4; i++) {
        int m = m0 + ty * 4 + i;
        if (m < Mn) {
            float4 vv;
            float* pv = (float*)&vv;
            #pragma unroll
            for (int j = 0; j < 4; j++) {
                float t = acc[i][j] + bias[n0 + tx * 4 + j];
                if (RELU) t = fmaxf(t, 0.f);
                pv[j] = t;
            }
            *(float4*)&C[(size_t)m * Nn + n0 + tx * 4] = vv;
        }
    }
}

// ---------------------------------------------------------------------------
// Fused flash attention. One block per (q-tile 64, head, batch).
// Q scaled by HD^-0.5 at load. Keys masked by pad mask / length.
// ---------------------------------------------------------------------------
__global__ __launch_bounds__(256) void attn_kernel() {
    extern __shared__ float sm[];
    float* Qs = sm;                    // [64][64] Qs[d*64+q]  (transposed)
    float* Ks = sm + 4096;             // [64][64] Ks[d*64+k]  (transposed)
    float* Vs = sm + 8192;             // [64][64] Vs[k*64+d]
    float* Pt = sm + 12288;            // [64][68] Pt[k*68+q]  (padded stride)
    float* km = sm + 12288 + 64 * 68;  // [64] key mask (1 = masked)

    int tid = threadIdx.x;
    int tx = tid & 15, ty = tid >> 4;
    int qt = blockIdx.x, h = blockIdx.y, b = blockIdx.z;
    int q0 = qt * 64;
    int ldr = tid >> 2;            // 0..63 (row loaded by this thread)
    int cb  = (tid & 3) * 16;      // column base (16 floats per thread)

    // Load Q tile transposed, pre-scaled
    {
        int qrow = q0 + ldr;
        bool valid = qrow < L_;
        const float* src = &g_q[((size_t)(b * L_) + (valid ? qrow : 0)) * D_ + h * HD_];
        #pragma unroll
        for (int u = 0; u < 16; u += 4) {
            float4 vv = valid ? *(const float4*)&src[cb + u]
                              : make_float4(0.f, 0.f, 0.f, 0.f);
            Qs[(cb + u + 0) * 64 + ldr] = vv.x * 0.125f;
            Qs[(cb + u + 1) * 64 + ldr] = vv.y * 0.125f;
            Qs[(cb + u + 2) * 64 + ldr] = vv.z * 0.125f;
            Qs[(cb + u + 3) * 64 + ldr] = vv.w * 0.125f;
        }
    }

    float o[4][4] = {};
    float mr[4]   = {-1e30f, -1e30f, -1e30f, -1e30f};
    float lsum[4] = {0.f, 0.f, 0.f, 0.f};

    const int NKT = (L_ + 63) / 64;  // 11
    for (int kt = 0; kt < NKT; kt++) {
        int k0 = kt * 64;
        __syncthreads();  // protect Vs/Pt/Qs from previous iter before overwrite

        {
            int krow = k0 + ldr;
            bool valid = krow < L_;
            const float* ksrc = &g_k[((size_t)(b * L_) + (valid ? krow : 0)) * D_ + h * HD_];
            const float* vsrc = &g_v[((size_t)(b * L_) + (valid ? krow : 0)) * D_ + h * HD_];
            #pragma unroll
            for (int u = 0; u < 16; u += 4) {
                float4 vv = valid ? *(const float4*)&ksrc[cb + u]
                                  : make_float4(0.f, 0.f, 0.f, 0.f);
                Ks[(cb + u + 0) * 64 + ldr] = vv.x;
                Ks[(cb + u + 1) * 64 + ldr] = vv.y;
                Ks[(cb + u + 2) * 64 + ldr] = vv.z;
                Ks[(cb + u + 3) * 64 + ldr] = vv.w;
            }
            #pragma unroll
            for (int u = 0; u < 16; u += 4) {
                float4 vv = valid ? *(const float4*)&vsrc[cb + u]
                                  : make_float4(0.f, 0.f, 0.f, 0.f);
                *(float4*)&Vs[ldr * 64 + cb + u] = vv;
            }
        }
        if (tid < 64) {
            int kp = k0 + tid;
            km[tid] = (kp < L_ && g_pad[b * L_ + kp] == 0) ? 0.f : 1.f;
        }
        __syncthreads();

        // S = Q^T K  (64x64, each thread 4x4)
        float s[4][4] = {};
        #pragma unroll 8
        for (int d = 0; d < 64; d++) {
            float4 a  = *(float4*)&Qs[d * 64 + ty * 4];
            float4 bb = *(float4*)&Ks[d * 64 + tx * 4];
            float ar[4] = {a.x, a.y, a.z, a.w};
            float br[4] = {bb.x, bb.y, bb.z, bb.w};
            #pragma unroll
            for (int i = 0; i < 4; i++)
                #pragma unroll
                for (int j = 0; j < 4; j++)
                    s[i][j] += ar[i] * br[j];
        }

        float kmr[4];
        #pragma unroll
        for (int j = 0; j < 4; j++) kmr[j] = km[tx * 4 + j];
        #pragma unroll
        for (int i = 0; i < 4; i++)
            #pragma unroll
            for (int j = 0; j < 4; j++)
                if (kmr[j] != 0.f) s[i][j] = -1e9f;

        // Online softmax (row stats shared across the 16 tx lanes)
        #pragma unroll
        for (int i = 0; i < 4; i++) {
            float tmax = fmaxf(fmaxf(s[i][0], s[i][1]), fmaxf(s[i][2], s[i][3]));
            #pragma unroll
            for (int off = 8; off >= 1; off >>= 1)
                tmax = fmaxf(tmax, __shfl_xor_sync(0xffffffffu, tmax, off));
            float mnew  = fmaxf(mr[i], tmax);
            float alpha = expf(mr[i] - mnew);
            float rsum = 0.f;
            #pragma unroll
            for (int j = 0; j < 4; j++) {
                float p = expf(s[i][j] - mnew);
                s[i][j] = p;
                rsum += p;
            }
            #pragma unroll
            for (int off = 8; off >= 1; off >>= 1)
                rsum += __shfl_xor_sync(0xffffffffu, rsum, off);
            lsum[i] = lsum[i] * alpha + rsum;
            mr[i] = mnew;
            #pragma unroll
            for (int j = 0; j < 4; j++) o[i][j] *= alpha;
        }

        // Write P transposed for the PV GEMM
        #pragma unroll
        for (int j = 0; j < 4; j++)
            #pragma unroll
            for (int i = 0; i < 4; i++)
                Pt[(tx * 4 + j) * 68 + ty * 4 + i] = s[i][j];
        __syncthreads();

        // O += P V
        #pragma unroll 8
        for (int kk = 0; kk < 64; kk++) {
            float4 a  = *(float4*)&Pt[kk * 68 + ty * 4];
            float4 bb = *(float4*)&Vs[kk * 64 + tx * 4];
            float ar[4] = {a.x, a.y, a.z, a.w};
            float br[4] = {bb.x, bb.y, bb.z, bb.w};
            #pragma unroll
            for (int i = 0; i < 4; i++)
                #pragma unroll
                for (int j = 0; j < 4; j++)
                    o[i][j] += ar[i] * br[j];
        }
    }

    #pragma unroll
    for (int i = 0; i < 4; i++) {
        int qrow = q0 + ty * 4 + i;
        if (qrow < L_) {
            float inv = 1.f / lsum[i];
            float4 vv = make_float4(o[i][0] * inv, o[i][1] * inv,
                                    o[i][2] * inv, o[i][3] * inv);
            *(float4*)&g_att[((size_t)(b * L_) + qrow) * D_ + h * HD_ + tx * 4] = vv;
        }
    }
}

// ---------------------------------------------------------------------------
// x = LayerNorm(x + y) * s + b  (in place on g_x; y = g_y)
// ---------------------------------------------------------------------------
__global__ __launch_bounds__(256) void add_ln_kernel(const float* __restrict__ sc,
                                                     const float* __restrict__ bi) {
    int row = blockIdx.x;
    float* xr = &g_x[(size_t)row * D_];
    const float* yr = &g_y[(size_t)row * D_];
    __shared__ float red[256];
    int tid = threadIdx.x;

    float v[4];
    float s = 0.f;
    #pragma unroll
    for (int u = 0; u < 4; u++) {
        int d = tid + u * 256;
        v[u] = xr[d] + yr[d];
        s += v[u];
    }
    red[tid] = s;
    __syncthreads();
    for (int off = 128; off > 0; off >>= 1) {
        if (tid < off) red[tid] += red[tid + off];
        __syncthreads();
    }
    float mean = red[0] * (1.f / D_);
    __syncthreads();

    float s2 = 0.f;
    #pragma unroll
    for (int u = 0; u < 4; u++) { float dd = v[u] - mean; s2 += dd * dd; }
    red[tid] = s2;
    __syncthreads();
    for (int off = 128; off > 0; off >>= 1) {
        if (tid < off) red[tid] += red[tid + off];
        __syncthreads();
    }
    float var = red[0] * (1.f / D_);
    float inv = rsqrtf(var + 1e-5f);

    #pragma unroll
    for (int u = 0; u < 4; u++) {
        int d = tid + u * 256;
        xr[d] = (v[u] - mean) * inv * sc[d] + bi[d];
    }
}

// ---------------------------------------------------------------------------
// out[b] = dot(x[b, 0, :], out_w)
// ---------------------------------------------------------------------------
__global__ __launch_bounds__(256) void final_kernel(const float* __restrict__ ow,
                                                    float* __restrict__ out) {
    int b = blockIdx.x;
    __shared__ float red[256];
    const float* xr = &g_x[(size_t)(b * L_) * D_];
    int tid = threadIdx.x;
    float s = 0.f;
    for (int d = tid; d < D_; d += 256) s += xr[d] * ow[d];
    red[tid] = s;
    __syncthreads();
    for (int off = 128; off > 0; off >>= 1) {
        if (tid < off) red[tid] += red[tid + off];
        __syncthreads();
    }
    if (tid == 0) out[b] = red[0];
}

// ---------------------------------------------------------------------------
// Launch
// ---------------------------------------------------------------------------
extern "C" void kernel_launch(void* const* d_in, const int* in_sizes, int n_in,
                              void* d_out, int out_size) {
    const float* text   = (const float*)d_in[0];
    const float* speech = (const float*)d_in[1];
    const void*  tmask  = d_in[2];
    const void*  smask  = d_in[3];
    const float* cls    = (const float*)d_in[4];
    const float* sep    = (const float*)d_in[5];
    const float* Wq     = (const float*)d_in[6];
    const float* bq     = (const float*)d_in[7];
    const float* Wk     = (const float*)d_in[8];
    const float* bk     = (const float*)d_in[9];
    const float* Wv     = (const float*)d_in[10];
    const float* bv     = (const float*)d_in[11];
    const float* Wo     = (const float*)d_in[12];
    const float* bo     = (const float*)d_in[13];
    const float* ln1s   = (const float*)d_in[14];
    const float* ln1b   = (const float*)d_in[15];
    const float* f1w    = (const float*)d_in[16];
    const float* f1b    = (const float*)d_in[17];
    const float* f2w    = (const float*)d_in[18];
    const float* f2b    = (const float*)d_in[19];
    const float* ln2s   = (const float*)d_in[20];
    const float* ln2b   = (const float*)d_in[21];
    const float* outw   = (const float*)d_in[22];
    float* out = (float*)d_out;

    float *x, *q, *k, *v, *att, *y, *hbuf;
    cudaGetSymbolAddress((void**)&x,    g_x);
    cudaGetSymbolAddress((void**)&q,    g_q);
    cudaGetSymbolAddress((void**)&k,    g_k);
    cudaGetSymbolAddress((void**)&v,    g_v);
    cudaGetSymbolAddress((void**)&att,  g_att);
    cudaGetSymbolAddress((void**)&y,    g_y);
    cudaGetSymbolAddress((void**)&hbuf, g_h);

    cudaFuncSetAttribute(attn_kernel,
                         cudaFuncAttributeMaxDynamicSharedMemorySize, SMEM_ATT);

    lengths_kernel<<<2, 256>>>(tmask, smask);
    build_x_kernel<<<dim3(L_, B_), 256>>>(text, speech, cls, sep);

    dim3 gD(D_ / 64, (M_ + 63) / 64);
    dim3 gF(F_ / 64, (M_ + 63) / 64);
    dim3 gAtt((L_ + 63) / 64, H_, B_);

    for (int l = 0; l < NL_; l++) {
        gemm_kernel<0><<<gD, 256>>>(x, Wq + (size_t)l * D_ * D_, bq + l * D_, q, M_, D_, D_);
        gemm_kernel<0><<<gD, 256>>>(x, Wk + (size_t)l * D_ * D_, bk + l * D_, k, M_, D_, D_);
        gemm_kernel<0><<<gD, 256>>>(x, Wv + (size_t)l * D_ * D_, bv + l * D_, v, M_, D_, D_);
        attn_kernel<<<gAtt, 256, SMEM_ATT>>>();
        gemm_kernel<0><<<gD, 256>>>(att, Wo + (size_t)l * D_ * D_, bo + l * D_, y, M_, D_, D_);
        add_ln_kernel<<<M_, 256>>>(ln1s + l * D_, ln1b + l * D_);
        gemm_kernel<1><<<gF, 256>>>(x, f1w + (size_t)l * D_ * F_, f1b + l * F_, hbuf, M_, F_, D_);
        gemm_kernel<0><<<gD, 256>>>(hbuf, f2w + (size_t)l * F_ * D_, f2b + l * D_, y, M_, D_, F_);
        add_ln_kernel<<<M_, 256>>>(ln2s + l * D_, ln2b + l * D_);
    }
    final_kernel<<<B_, 256>>>(outw, out);
}